// round 10
// baseline (speedup 1.0000x reference)
#include <cuda_runtime.h>
#include <cstdint>

#define BSZ   4096
#define NNODE 16
#define OBSP  10
#define HID   128
#define GPB   4          // graphs per CTA (one warp each)
#define NTH   128
#define BROW  272        // A-tile row pitch in bytes (16 rows x 136 bf16)

typedef unsigned long long ull;
typedef unsigned int u32;

// ---- B fragments in gmem, exact mma operand order, built by prep kernel ----
// [head][np(16-col tile)][ks][lane] = {b0_t0, b1_t0, b0_t1, b1_t1}
__device__ uint4 g_bfragH[2][8][8][32];
__device__ uint4 g_bfragL[2][8][8][32];

// ---------------- mma.sync / ldmatrix (sm_80+ portable) ----------------
#define LDSM_X4(r, addr) \
    asm volatile("ldmatrix.sync.aligned.m8n8.x4.shared.b16 {%0,%1,%2,%3}, [%4];" \
        : "=r"((r)[0]), "=r"((r)[1]), "=r"((r)[2]), "=r"((r)[3]) : "r"(addr))
#define MMA_BF16(d, a, b0, b1) \
    asm volatile("mma.sync.aligned.m16n8k16.row.col.f32.bf16.bf16.f32 " \
        "{%0,%1,%2,%3}, {%4,%5,%6,%7}, {%8,%9}, {%0,%1,%2,%3};" \
        : "+f"((d)[0]), "+f"((d)[1]), "+f"((d)[2]), "+f"((d)[3]) \
        : "r"((a)[0]), "r"((a)[1]), "r"((a)[2]), "r"((a)[3]), "r"(b0), "r"(b1))

__device__ __forceinline__ u32 smem_u32(const void* p) {
    u32 a;
    asm("{ .reg .u64 t; cvta.to.shared.u64 t, %1; cvt.u32.u64 %0, t; }" : "=r"(a) : "l"(p));
    return a;
}
// ---- packed f32x2 + bf16 helpers ----
__device__ __forceinline__ ull pk2(float lo, float hi) {
    ull r; asm("mov.b64 %0, {%1, %2};" : "=l"(r) : "f"(lo), "f"(hi)); return r;
}
__device__ __forceinline__ void upk2(ull v, float& lo, float& hi) {
    asm("mov.b64 {%0, %1}, %2;" : "=f"(lo), "=f"(hi) : "l"(v));
}
__device__ __forceinline__ void ffma2(ull& d, ull a, ull b) {
    asm("fma.rn.f32x2 %0, %1, %2, %0;" : "+l"(d) : "l"(a), "l"(b));
}
__device__ __forceinline__ u32 packbf(float hi_el, float lo_el) {
    u32 r; asm("cvt.rn.bf16x2.f32 %0, %1, %2;" : "=r"(r) : "f"(hi_el), "f"(lo_el));
    return r;
}
__device__ __forceinline__ float bf_lo(u32 w) { return __uint_as_float(w << 16); }
__device__ __forceinline__ float bf_hi(u32 w) { return __uint_as_float(w & 0xffff0000u); }

// ---------------- pre-kernel: W1 -> bf16 hi/lo fragments ----------------
__global__ void __launch_bounds__(256)
prep_bfrag(const float* __restrict__ W1a, const float* __restrict__ W1b)
{
    int id = blockIdx.x * 256 + threadIdx.x;      // 0..4095
    int h  = id >> 11, np = (id >> 8) & 7, ks = (id >> 5) & 7, l = id & 31;
    const float* W1 = h ? W1b : W1a;
    int n0 = 16 * np + (l >> 2);
    int n1 = n0 + 8;
    int k0 = 16 * ks + (l & 3) * 2;
    float f00 = W1[k0 * HID + n0],       f01 = W1[(k0 + 1) * HID + n0];
    float f02 = W1[(k0 + 8) * HID + n0], f03 = W1[(k0 + 9) * HID + n0];
    float f10 = W1[k0 * HID + n1],       f11 = W1[(k0 + 1) * HID + n1];
    float f12 = W1[(k0 + 8) * HID + n1], f13 = W1[(k0 + 9) * HID + n1];
    u32 h0 = packbf(f01, f00), h1 = packbf(f03, f02);
    u32 h2 = packbf(f11, f10), h3 = packbf(f13, f12);
    u32 l0 = packbf(f01 - bf_hi(h0), f00 - bf_lo(h0));
    u32 l1 = packbf(f03 - bf_hi(h1), f02 - bf_lo(h1));
    u32 l2 = packbf(f11 - bf_hi(h2), f10 - bf_lo(h2));
    u32 l3 = packbf(f13 - bf_hi(h3), f12 - bf_lo(h3));
    g_bfragH[h][np][ks][l] = make_uint4(h0, h1, h2, h3);
    g_bfragL[h][np][ks][l] = make_uint4(l0, l1, l2, l3);
}

// ---------------- main kernel ----------------
struct __align__(16) PG {
    char  Areg[8704];          // Ahi[16][BROW], Alo at +4352; aliases:
                               //   Ys fp32 [16][132] (8448B); y2s at +8448;
                               //   preamble scratch
    float A[NNODE][NNODE];     // normalized adjacency (symmetric)
    float Xat[OBSP][NNODE];    // (A@X) transposed
};

#define LOADROW8(dst, ptr) do { \
    const ulonglong2* _p = reinterpret_cast<const ulonglong2*>(ptr); \
    ulonglong2 _a = _p[0], _b = _p[1], _c = _p[2], _d = _p[3]; \
    dst[0]=_a.x; dst[1]=_a.y; dst[2]=_b.x; dst[3]=_b.y; \
    dst[4]=_c.x; dst[5]=_c.y; dst[6]=_d.x; dst[7]=_d.y; } while(0)

__global__ void __launch_bounds__(NTH, 4)
gcn_mma3(const float* __restrict__ obs, const float* __restrict__ act,
         const float* __restrict__ Q1W0, const float* __restrict__ Q1b0,
         const float* __restrict__ Q1b1, const float* __restrict__ Q1W2,
         const float* __restrict__ Q1b2,
         const float* __restrict__ Q2W0, const float* __restrict__ Q2b0,
         const float* __restrict__ Q2b1, const float* __restrict__ Q2W2,
         const float* __restrict__ Q2b2,
         float* __restrict__ out)
{
    __shared__ PG pg[GPB];
    const int tid  = threadIdx.x;
    const int warp = tid >> 5;
    const int lane = tid & 31;
    PG& P = pg[warp];
    const int g = blockIdx.x * GPB + warp;

    const u32 GAhi = smem_u32(P.Areg);
    const u32 GAlo = GAhi + 4352;
    float* Ys  = reinterpret_cast<float*>(P.Areg);          // [16][132] fp32
    float* y2s = reinterpret_cast<float*>(P.Areg + 8448);   // [16]

    // ---- per-graph preamble (warp-private; scratch inside Areg)
    {
        float* Xt   = reinterpret_cast<float*>(P.Areg);
        float* lx   = Xt + 160;
        float* ly   = Xt + 176;
        float* dinv = Xt + 192;
        const float* ob = obs + (size_t)g * (NNODE * OBSP);
        #pragma unroll
        for (int r = 0; r < 5; r++) {
            int idx = lane + 32 * r;
            float v = ob[idx];
            int n = idx / OBSP, k = idx - n * OBSP;
            if (k == 0)      lx[n] = v;
            else if (k == 1) ly[n] = v;
            else             Xt[(k - 2) * NNODE + n] = v;
        }
        float v = act[(size_t)g * (NNODE * 2) + lane];
        Xt[(8 + (lane & 1)) * NNODE + (lane >> 1)] = v;
        __syncwarp();
        #pragma unroll
        for (int r = 0; r < 8; r++) {
            int e = lane * 8 + r, i = e >> 4, j = e & 15;
            float dx = lx[i] - lx[j], dy = ly[i] - ly[j];
            P.A[i][j] = expf(-sqrtf(dx * dx + dy * dy));
        }
        __syncwarp();
        if (lane < NNODE) {
            float s = 0.f;
            #pragma unroll
            for (int j = 0; j < NNODE; j++) s += P.A[j][lane];
            dinv[lane] = rsqrtf(s);               // deg >= 1 (self loop)
        }
        __syncwarp();
        #pragma unroll
        for (int r = 0; r < 8; r++) {
            int e = lane * 8 + r, i = e >> 4, j = e & 15;
            P.A[i][j] *= dinv[i] * dinv[j];
        }
        __syncwarp();
        #pragma unroll
        for (int r = 0; r < 5; r++) {
            int idx = lane + 32 * r;              // 160 = 16 x 10
            int i = idx / OBSP, k = idx - i * OBSP;
            float s = 0.f;
            #pragma unroll
            for (int j = 0; j < NNODE; j++) s = fmaf(P.A[i][j], Xt[k * NNODE + j], s);
            P.Xat[k][i] = s;
        }
        __syncwarp();
    }

    // ---- Amat bf16 hi/lo A-fragments for agg1 (held in regs all kernel)
    const int gid = lane >> 2, tig = lane & 3;
    u32 ahA[4], alA[4];
    {
        #pragma unroll
        for (int t = 0; t < 4; t++) {
            int r  = gid + (t & 1) * 8;
            int kc = 2 * tig + (t >> 1) * 8;
            float f0 = P.A[r][kc], f1 = P.A[r][kc + 1];
            ahA[t] = packbf(f1, f0);
            alA[t] = packbf(f1 - bf_hi(ahA[t]), f0 - bf_lo(ahA[t]));
        }
    }

    #pragma unroll 1
    for (int q = 0; q < 2; q++) {
        const float* W0 = q ? Q2W0 : Q1W0;
        const float* B0 = q ? Q2b0 : Q1b0;
        const float* B1 = q ? Q2b1 : Q1b1;
        const float* W2 = q ? Q2W2 : Q1W2;
        const float* B2 = q ? Q2b2 : Q1b2;

        // ==== GEMM0 (scalar fp32): y0 = Xa @ W0; relu(+b0) -> Ahi/Alo (bf16 split)
        {
            ull acc[32];
            #pragma unroll
            for (int p = 0; p < 32; p++) acc[p] = 0ull;
            #pragma unroll
            for (int k = 0; k < OBSP; k++) {
                float4 w4 = __ldg(reinterpret_cast<const float4*>(W0 + k * HID) + lane);
                ull row[8]; LOADROW8(row, &P.Xat[k][0]);
                ull wd;
                wd = pk2(w4.x, w4.x);
                #pragma unroll
                for (int m = 0; m < 8; m++) ffma2(acc[m],      row[m], wd);
                wd = pk2(w4.y, w4.y);
                #pragma unroll
                for (int m = 0; m < 8; m++) ffma2(acc[8 + m],  row[m], wd);
                wd = pk2(w4.z, w4.z);
                #pragma unroll
                for (int m = 0; m < 8; m++) ffma2(acc[16 + m], row[m], wd);
                wd = pk2(w4.w, w4.w);
                #pragma unroll
                for (int m = 0; m < 8; m++) ffma2(acc[24 + m], row[m], wd);
            }
            __syncwarp();   // prior-phase Ys/y2s reads done before overwrite
            float4 b0v = __ldg(reinterpret_cast<const float4*>(B0) + lane);
            float bc[4] = {b0v.x, b0v.y, b0v.z, b0v.w};
            #pragma unroll
            for (int m = 0; m < 8; m++) {
                float va[4], vb[4];
                #pragma unroll
                for (int c = 0; c < 4; c++) upk2(acc[c * 8 + m], va[c], vb[c]);
                #pragma unroll
                for (int rr = 0; rr < 2; rr++) {
                    const float* v = rr ? vb : va;
                    int row = 2 * m + rr;
                    float h0 = fmaxf(v[0] + bc[0], 0.f), h1 = fmaxf(v[1] + bc[1], 0.f);
                    float h2 = fmaxf(v[2] + bc[2], 0.f), h3 = fmaxf(v[3] + bc[3], 0.f);
                    u32 p0 = packbf(h1, h0), p1 = packbf(h3, h2);
                    u32 q0 = packbf(h1 - bf_hi(p0), h0 - bf_lo(p0));
                    u32 q1 = packbf(h3 - bf_hi(p1), h2 - bf_lo(p1));
                    *reinterpret_cast<uint2*>(P.Areg + row * BROW + lane * 8)
                        = make_uint2(p0, p1);
                    *reinterpret_cast<uint2*>(P.Areg + 4352 + row * BROW + lane * 8)
                        = make_uint2(q0, q1);
                }
            }
        }
        __syncwarp();

        // ==== GEMM1 (tensor): y1 = h0 @ W1, 3-term bf16 split, single merged pass
        {
            u32 ah[8][4], al[8][4];
            const u32 arow = (u32)(lane & 15) * BROW + (u32)(lane >> 4) * 16;
            #pragma unroll
            for (int ks = 0; ks < 8; ks++) {
                LDSM_X4(ah[ks], GAhi + arow + ks * 32);
                LDSM_X4(al[ks], GAlo + arow + ks * 32);
            }
            __syncwarp();   // all A frags in regs before Ys overwrites the tiles
            const uint4* BH = &g_bfragH[q][0][0][lane];
            const uint4* BL = &g_bfragL[q][0][0][lane];

            #pragma unroll 1
            for (int np = 0; np < 8; np++) {
                float d0[4] = {0,0,0,0}, d1[4] = {0,0,0,0};
                #pragma unroll
                for (int ks = 0; ks < 8; ks++) {
                    uint4 v = __ldg(BH + (np * 8 + ks) * 32);
                    uint4 w = __ldg(BL + (np * 8 + ks) * 32);
                    MMA_BF16(d0, ah[ks], v.x, v.y);
                    MMA_BF16(d0, al[ks], v.x, v.y);
                    MMA_BF16(d0, ah[ks], w.x, w.y);
                    MMA_BF16(d1, ah[ks], v.z, v.w);
                    MMA_BF16(d1, al[ks], v.z, v.w);
                    MMA_BF16(d1, ah[ks], w.z, w.w);
                }
                #pragma unroll
                for (int t2 = 0; t2 < 2; t2++) {
                    float* d = t2 ? d1 : d0;
                    int col = 16 * np + 8 * t2 + 2 * tig;
                    *reinterpret_cast<float2*>(&Ys[gid * 132 + col])
                        = make_float2(d[0], d[1]);
                    *reinterpret_cast<float2*>(&Ys[(gid + 8) * 132 + col])
                        = make_float2(d[2], d[3]);
                }
            }
        }
        __syncwarp();   // cross-lane Ys visibility for agg1

        // ==== agg1 (tensor): D2 = Amat @ y1; relu(+b1); dot W2 -> y2
        {
            float part0 = 0.f, part1 = 0.f;   // rows gid, gid+8
            #pragma unroll 1
            for (int nt = 0; nt < 16; nt++) {
                int n = 8 * nt + gid;
                // y1 B-fragment (k = 2tig..2tig+1, 2tig+8..+9 at col n), fp32 -> split
                float y00 = Ys[(2 * tig)     * 132 + n];
                float y01 = Ys[(2 * tig + 1) * 132 + n];
                float y10 = Ys[(2 * tig + 8) * 132 + n];
                float y11 = Ys[(2 * tig + 9) * 132 + n];
                u32 bh0 = packbf(y01, y00);
                u32 bh1 = packbf(y11, y10);
                u32 bl0 = packbf(y01 - bf_hi(bh0), y00 - bf_lo(bh0));
                u32 bl1 = packbf(y11 - bf_hi(bh1), y10 - bf_lo(bh1));
                float d[4] = {0, 0, 0, 0};
                MMA_BF16(d, ahA, bh0, bh1);
                MMA_BF16(d, alA, bh0, bh1);
                MMA_BF16(d, ahA, bl0, bl1);
                // epilogue: cols 8nt+2tig, +1; rows gid (d0,d1), gid+8 (d2,d3)
                float2 b1v = __ldg(reinterpret_cast<const float2*>(B1 + 8 * nt) + tig);
                float2 w2v = __ldg(reinterpret_cast<const float2*>(W2 + 8 * nt) + tig);
                part0 = fmaf(fmaxf(d[0] + b1v.x, 0.f), w2v.x, part0);
                part0 = fmaf(fmaxf(d[1] + b1v.y, 0.f), w2v.y, part0);
                part1 = fmaf(fmaxf(d[2] + b1v.x, 0.f), w2v.x, part1);
                part1 = fmaf(fmaxf(d[3] + b1v.y, 0.f), w2v.y, part1);
            }
            // reduce over tig (lanes gid*4 + tig)
            part0 += __shfl_xor_sync(0xffffffffu, part0, 1);
            part0 += __shfl_xor_sync(0xffffffffu, part0, 2);
            part1 += __shfl_xor_sync(0xffffffffu, part1, 1);
            part1 += __shfl_xor_sync(0xffffffffu, part1, 2);
            if (tig == 0) {
                y2s[gid]     = part0;
                y2s[gid + 8] = part1;
            }
            __syncwarp();

            // ==== final agg: out[i] = b2 + sum_j A[j][i] * y2[j]
            if (lane < NNODE) {
                float o = __ldg(B2);
                #pragma unroll
                for (int j = 0; j < NNODE; j++)
                    o = fmaf(P.A[j][lane], y2s[j], o);
                out[(size_t)q * BSZ * NNODE + (size_t)g * NNODE + lane] = o;
            }
        }
        __syncwarp();   // Ys/y2s dead before next head's epilogue overwrites Areg
    }
}

extern "C" void kernel_launch(void* const* d_in, const int* in_sizes, int n_in,
                              void* d_out, int out_size)
{
    (void)in_sizes; (void)n_in; (void)out_size;
    prep_bfrag<<<16, 256>>>((const float*)d_in[4], (const float*)d_in[10]);
    gcn_mma3<<<BSZ / GPB, NTH>>>(
        (const float*)d_in[0],  (const float*)d_in[1],
        (const float*)d_in[2],  (const float*)d_in[3],   // Q1W0, Q1b0
        (const float*)d_in[5],                            // Q1b1
        (const float*)d_in[6],  (const float*)d_in[7],   // Q1W2, Q1b2
        (const float*)d_in[8],  (const float*)d_in[9],   // Q2W0, Q2b0
        (const float*)d_in[11],                           // Q2b1
        (const float*)d_in[12], (const float*)d_in[13],  // Q2W2, Q2b2
        (float*)d_out);
}

// round 11
// speedup vs baseline: 1.0096x; 1.0096x over previous
#include <cuda_runtime.h>
#include <cstdint>

#define BSZ   4096
#define NNODE 16
#define OBSP  10
#define HID   128
#define GPB   4          // graphs per CTA (one warp each)
#define NTH   128

typedef unsigned long long ull;
typedef unsigned int u32;

// ---- B fragments in gmem, exact mma operand order, built by prep kernels ----
// W1: [head][np(16-col tile)][ks][lane] = {b0_t0, b1_t0, b0_t1, b1_t1}
__device__ uint4 g_bfragH[2][8][8][32];
__device__ uint4 g_bfragL[2][8][8][32];
// W0 (k=10 zero-padded to 16): [head][np][lane]
__device__ uint4 g_b0H[2][8][32];
__device__ uint4 g_b0L[2][8][32];

// ---------------- mma.sync (sm_80+ portable) ----------------
#define MMA_BF16(d, a, b0, b1) \
    asm volatile("mma.sync.aligned.m16n8k16.row.col.f32.bf16.bf16.f32 " \
        "{%0,%1,%2,%3}, {%4,%5,%6,%7}, {%8,%9}, {%0,%1,%2,%3};" \
        : "+f"((d)[0]), "+f"((d)[1]), "+f"((d)[2]), "+f"((d)[3]) \
        : "r"((a)[0]), "r"((a)[1]), "r"((a)[2]), "r"((a)[3]), "r"(b0), "r"(b1))

// ---- packed f32x2 + bf16 helpers ----
__device__ __forceinline__ ull pk2(float lo, float hi) {
    ull r; asm("mov.b64 %0, {%1, %2};" : "=l"(r) : "f"(lo), "f"(hi)); return r;
}
__device__ __forceinline__ void upk2(ull v, float& lo, float& hi) {
    asm("mov.b64 {%0, %1}, %2;" : "=f"(lo), "=f"(hi) : "l"(v));
}
__device__ __forceinline__ void ffma2(ull& d, ull a, ull b) {
    asm("fma.rn.f32x2 %0, %1, %2, %0;" : "+l"(d) : "l"(a), "l"(b));
}
__device__ __forceinline__ void add2(ull& d, ull a) {
    asm("add.rn.f32x2 %0, %0, %1;" : "+l"(d) : "l"(a));
}
__device__ __forceinline__ u32 packbf(float hi_el, float lo_el) {
    u32 r; asm("cvt.rn.bf16x2.f32 %0, %1, %2;" : "=r"(r) : "f"(hi_el), "f"(lo_el));
    return r;
}
__device__ __forceinline__ float bf_lo(u32 w) { return __uint_as_float(w << 16); }
__device__ __forceinline__ float bf_hi(u32 w) { return __uint_as_float(w & 0xffff0000u); }
// split pair (f0,f1) -> hi bf16x2 + lo residual bf16x2
__device__ __forceinline__ void split2(float f0, float f1, u32& hi, u32& lo) {
    hi = packbf(f1, f0);
    lo = packbf(f1 - bf_hi(hi), f0 - bf_lo(hi));
}

// ---------------- prep kernel 1: W1 -> bf16 hi/lo fragments ----------------
__global__ void __launch_bounds__(256)
prep_bfrag(const float* __restrict__ W1a, const float* __restrict__ W1b)
{
    int id = blockIdx.x * 256 + threadIdx.x;      // 0..4095
    int h  = id >> 11, np = (id >> 8) & 7, ks = (id >> 5) & 7, l = id & 31;
    const float* W1 = h ? W1b : W1a;
    int n0 = 16 * np + (l >> 2);
    int n1 = n0 + 8;
    int k0 = 16 * ks + (l & 3) * 2;
    u32 h0, h1, h2, h3, l0, l1, l2, l3;
    split2(W1[k0 * HID + n0],       W1[(k0 + 1) * HID + n0], h0, l0);
    split2(W1[(k0 + 8) * HID + n0], W1[(k0 + 9) * HID + n0], h1, l1);
    split2(W1[k0 * HID + n1],       W1[(k0 + 1) * HID + n1], h2, l2);
    split2(W1[(k0 + 8) * HID + n1], W1[(k0 + 9) * HID + n1], h3, l3);
    g_bfragH[h][np][ks][l] = make_uint4(h0, h1, h2, h3);
    g_bfragL[h][np][ks][l] = make_uint4(l0, l1, l2, l3);
}

// ---------------- prep kernel 2: W0 (k 10->16 zero-pad) ----------------
__global__ void __launch_bounds__(256)
prep_b0frag(const float* __restrict__ W0a, const float* __restrict__ W0b)
{
    int id = blockIdx.x * 256 + threadIdx.x;      // 0..511
    int h  = id >> 8, np = (id >> 5) & 7, l = id & 31;
    const float* W0 = h ? W0b : W0a;
    int n0 = 16 * np + (l >> 2);
    int n1 = n0 + 8;
    int tig = l & 3;
    int k0 = 2 * tig;                              // 0,2,4,6 (k0+1 <= 7 < 10)
    u32 h0, h1, h2, h3, l0, l1, l2, l3;
    split2(W0[k0 * HID + n0], W0[(k0 + 1) * HID + n0], h0, l0);
    split2(W0[k0 * HID + n1], W0[(k0 + 1) * HID + n1], h2, l2);
    if (tig == 0) {                                // k0+8 = 8,9 valid only here
        split2(W0[8 * HID + n0], W0[9 * HID + n0], h1, l1);
        split2(W0[8 * HID + n1], W0[9 * HID + n1], h3, l3);
    } else { h1 = l1 = h3 = l3 = 0u; }
    g_b0H[h][np][l] = make_uint4(h0, h1, h2, h3);
    g_b0L[h][np][l] = make_uint4(l0, l1, l2, l3);
}

// ---------------- main kernel ----------------
struct __align__(16) PG {
    float Ys[NNODE * 132];     // y1 fp32 [16][132]; preamble scratch aliases
    float A[NNODE][NNODE];     // normalized adjacency (symmetric)
    float Xat[OBSP][NNODE];    // (A@X) transposed
};

#define LOADROW8(dst, ptr) do { \
    const ulonglong2* _p = reinterpret_cast<const ulonglong2*>(ptr); \
    ulonglong2 _a = _p[0], _b = _p[1], _c = _p[2], _d = _p[3]; \
    dst[0]=_a.x; dst[1]=_a.y; dst[2]=_b.x; dst[3]=_b.y; \
    dst[4]=_c.x; dst[5]=_c.y; dst[6]=_d.x; dst[7]=_d.y; } while(0)

__global__ void __launch_bounds__(NTH, 4)
gcn_mma4(const float* __restrict__ obs, const float* __restrict__ act,
         const float* __restrict__ Q1b0, const float* __restrict__ Q1b1,
         const float* __restrict__ Q1W2, const float* __restrict__ Q1b2,
         const float* __restrict__ Q2b0, const float* __restrict__ Q2b1,
         const float* __restrict__ Q2W2, const float* __restrict__ Q2b2,
         float* __restrict__ out)
{
    __shared__ PG pg[GPB];
    const int tid  = threadIdx.x;
    const int warp = tid >> 5;
    const int lane = tid & 31;
    PG& P = pg[warp];
    const int g = blockIdx.x * GPB + warp;
    const int gid = lane >> 2, tig = lane & 3;
    float* Ys = P.Ys;

    // ---- per-graph preamble (warp-private; scratch aliases Ys region)
    {
        float* Xt   = P.Ys;            // [10][16]
        float* lx   = Xt + 160;
        float* ly   = Xt + 176;
        float* dinv = Xt + 192;
        const float* ob = obs + (size_t)g * (NNODE * OBSP);
        #pragma unroll
        for (int r = 0; r < 5; r++) {
            int idx = lane + 32 * r;
            float v = ob[idx];
            int n = idx / OBSP, k = idx - n * OBSP;
            if (k == 0)      lx[n] = v;
            else if (k == 1) ly[n] = v;
            else             Xt[(k - 2) * NNODE + n] = v;
        }
        float v = act[(size_t)g * (NNODE * 2) + lane];
        Xt[(8 + (lane & 1)) * NNODE + (lane >> 1)] = v;
        __syncwarp();
        #pragma unroll
        for (int r = 0; r < 8; r++) {
            int e = lane * 8 + r, i = e >> 4, j = e & 15;
            float dx = lx[i] - lx[j], dy = ly[i] - ly[j];
            P.A[i][j] = expf(-sqrtf(dx * dx + dy * dy));
        }
        __syncwarp();
        if (lane < NNODE) {
            float s = 0.f;
            #pragma unroll
            for (int j = 0; j < NNODE; j++) s += P.A[j][lane];
            dinv[lane] = rsqrtf(s);               // deg >= 1 (self loop)
        }
        __syncwarp();
        #pragma unroll
        for (int r = 0; r < 8; r++) {
            int e = lane * 8 + r, i = e >> 4, j = e & 15;
            P.A[i][j] *= dinv[i] * dinv[j];
        }
        __syncwarp();
        #pragma unroll
        for (int r = 0; r < 5; r++) {
            int idx = lane + 32 * r;              // 160 = 16 x 10
            int i = idx / OBSP, k = idx - i * OBSP;
            float s = 0.f;
            #pragma unroll
            for (int j = 0; j < NNODE; j++) s = fmaf(P.A[i][j], Xt[k * NNODE + j], s);
            P.Xat[k][i] = s;
        }
        __syncwarp();
    }

    // ---- Xa A-fragments (bf16 hi/lo, k 10 zero-padded to 16); reused both heads
    u32 ahX[4], alX[4];
    {
        split2(P.Xat[2 * tig][gid],     P.Xat[2 * tig + 1][gid],     ahX[0], alX[0]);
        split2(P.Xat[2 * tig][gid + 8], P.Xat[2 * tig + 1][gid + 8], ahX[1], alX[1]);
        if (tig == 0) {
            split2(P.Xat[8][gid],     P.Xat[9][gid],     ahX[2], alX[2]);
            split2(P.Xat[8][gid + 8], P.Xat[9][gid + 8], ahX[3], alX[3]);
        } else { ahX[2] = alX[2] = ahX[3] = alX[3] = 0u; }
    }

    #pragma unroll 1
    for (int q = 0; q < 2; q++) {
        const float* B0 = q ? Q2b0 : Q1b0;
        const float* B1 = q ? Q2b1 : Q1b1;
        const float* W2 = q ? Q2W2 : Q1W2;
        const float* B2 = q ? Q2b2 : Q1b2;

        // ==== GEMM0 (tensor): h0 = relu(Xa @ W0 + b0); D-frags become GEMM1 A-frags
        u32 ah[8][4], al[8][4];
        {
            const uint4* B0H = &g_b0H[q][0][lane];
            const uint4* B0L = &g_b0L[q][0][lane];
            #pragma unroll
            for (int np = 0; np < 8; np++) {
                float d0[4] = {0,0,0,0}, d1[4] = {0,0,0,0};
                uint4 v = __ldg(B0H + np * 32);
                uint4 w = __ldg(B0L + np * 32);
                MMA_BF16(d0, ahX, v.x, v.y);
                MMA_BF16(d0, alX, v.x, v.y);
                MMA_BF16(d0, ahX, w.x, w.y);
                MMA_BF16(d1, ahX, v.z, v.w);
                MMA_BF16(d1, alX, v.z, v.w);
                MMA_BF16(d1, ahX, w.z, w.w);
                // bias + relu; cols: d0 -> 16np+2tig,+1 ; d1 -> 16np+8+2tig,+1
                float2 b00 = __ldg(reinterpret_cast<const float2*>(B0) + 8 * np + tig);
                float2 b01 = __ldg(reinterpret_cast<const float2*>(B0) + 8 * np + 4 + tig);
                float h00 = fmaxf(d0[0] + b00.x, 0.f), h01 = fmaxf(d0[1] + b00.y, 0.f);
                float h02 = fmaxf(d0[2] + b00.x, 0.f), h03 = fmaxf(d0[3] + b00.y, 0.f);
                float h10 = fmaxf(d1[0] + b01.x, 0.f), h11 = fmaxf(d1[1] + b01.y, 0.f);
                float h12 = fmaxf(d1[2] + b01.x, 0.f), h13 = fmaxf(d1[3] + b01.y, 0.f);
                // D-frag == A-frag of GEMM1 k-tile np (rows gid/gid+8, k 2tig / +8)
                split2(h00, h01, ah[np][0], al[np][0]);
                split2(h02, h03, ah[np][1], al[np][1]);
                split2(h10, h11, ah[np][2], al[np][2]);
                split2(h12, h13, ah[np][3], al[np][3]);
            }
        }
        __syncwarp();   // prior head's Ys reads done before GEMM1 stores below

        // ==== GEMM1 (tensor): y1 = h0 @ W1, 3-term bf16 split, split accumulators
        {
            const uint4* BH = &g_bfragH[q][0][0][lane];
            const uint4* BL = &g_bfragL[q][0][0][lane];
            #pragma unroll 1
            for (int np = 0; np < 8; np++) {
                float d0[4] = {0,0,0,0}, e0[4] = {0,0,0,0};
                float d1[4] = {0,0,0,0}, e1[4] = {0,0,0,0};
                #pragma unroll
                for (int ks = 0; ks < 8; ks++) {
                    uint4 v = __ldg(BH + (np * 8 + ks) * 32);
                    uint4 w = __ldg(BL + (np * 8 + ks) * 32);
                    MMA_BF16(d0, ah[ks], v.x, v.y);
                    MMA_BF16(e0, al[ks], v.x, v.y);
                    MMA_BF16(e0, ah[ks], w.x, w.y);
                    MMA_BF16(d1, ah[ks], v.z, v.w);
                    MMA_BF16(e1, al[ks], v.z, v.w);
                    MMA_BF16(e1, ah[ks], w.z, w.w);
                }
                int col0 = 16 * np + 2 * tig;
                *reinterpret_cast<float2*>(&Ys[gid * 132 + col0])
                    = make_float2(d0[0] + e0[0], d0[1] + e0[1]);
                *reinterpret_cast<float2*>(&Ys[(gid + 8) * 132 + col0])
                    = make_float2(d0[2] + e0[2], d0[3] + e0[3]);
                *reinterpret_cast<float2*>(&Ys[gid * 132 + col0 + 8])
                    = make_float2(d1[0] + e1[0], d1[1] + e1[1]);
                *reinterpret_cast<float2*>(&Ys[(gid + 8) * 132 + col0 + 8])
                    = make_float2(d1[2] + e1[2], d1[3] + e1[3]);
            }
        }
        __syncwarp();   // cross-lane Ys visibility for agg1

        // ==== agg1 (scalar, proven): A @ y1; relu(+b1); dot W2; reduce; final agg
        {
            ull acc2[32];
            #pragma unroll
            for (int p = 0; p < 32; p++) acc2[p] = 0ull;
            #pragma unroll 4
            for (int j = 0; j < NNODE; j++) {
                float4 y4 = *reinterpret_cast<const float4*>(&Ys[j * 132 + 4 * lane]);
                ull ar[8]; LOADROW8(ar, &P.A[j][0]);
                ull yd;
                yd = pk2(y4.x, y4.x);
                #pragma unroll
                for (int m = 0; m < 8; m++) ffma2(acc2[m],      ar[m], yd);
                yd = pk2(y4.y, y4.y);
                #pragma unroll
                for (int m = 0; m < 8; m++) ffma2(acc2[8 + m],  ar[m], yd);
                yd = pk2(y4.z, y4.z);
                #pragma unroll
                for (int m = 0; m < 8; m++) ffma2(acc2[16 + m], ar[m], yd);
                yd = pk2(y4.w, y4.w);
                #pragma unroll
                for (int m = 0; m < 8; m++) ffma2(acc2[24 + m], ar[m], yd);
            }
            ull part[8];
            #pragma unroll
            for (int m = 0; m < 8; m++) part[m] = 0ull;
            {
                float4 b1v = __ldg(reinterpret_cast<const float4*>(B1) + lane);
                float4 w2v = __ldg(reinterpret_cast<const float4*>(W2) + lane);
                float bc[4] = {b1v.x, b1v.y, b1v.z, b1v.w};
                float wc[4] = {w2v.x, w2v.y, w2v.z, w2v.w};
                #pragma unroll
                for (int c = 0; c < 4; c++) {
                    ull w2d = pk2(wc[c], wc[c]);
                    #pragma unroll
                    for (int m = 0; m < 8; m++) {
                        float lo, hi; upk2(acc2[c * 8 + m], lo, hi);
                        lo = fmaxf(lo + bc[c], 0.f);
                        hi = fmaxf(hi + bc[c], 0.f);
                        ffma2(part[m], pk2(lo, hi), w2d);
                    }
                }
            }
            #pragma unroll
            for (int off = 16; off > 0; off >>= 1) {
                #pragma unroll
                for (int m = 0; m < 8; m++) {
                    ull o = __shfl_xor_sync(0xffffffffu, part[m], off);
                    add2(part[m], o);
                }
            }
            if (lane < NNODE) {
                float y2[16];
                #pragma unroll
                for (int m = 0; m < 8; m++) upk2(part[m], y2[2 * m], y2[2 * m + 1]);
                float o = __ldg(B2);
                #pragma unroll
                for (int j = 0; j < NNODE; j++)
                    o = fmaf(P.A[j][lane], y2[j], o);
                out[(size_t)q * BSZ * NNODE + (size_t)g * NNODE + lane] = o;
            }
        }
        __syncwarp();   // Ys dead before next head's GEMM1 stores
    }
}

extern "C" void kernel_launch(void* const* d_in, const int* in_sizes, int n_in,
                              void* d_out, int out_size)
{
    (void)in_sizes; (void)n_in; (void)out_size;
    prep_bfrag<<<16, 256>>>((const float*)d_in[4], (const float*)d_in[10]);
    prep_b0frag<<<2, 256>>>((const float*)d_in[2], (const float*)d_in[8]);
    gcn_mma4<<<BSZ / GPB, NTH>>>(
        (const float*)d_in[0],  (const float*)d_in[1],
        (const float*)d_in[3],  (const float*)d_in[5],   // Q1b0, Q1b1
        (const float*)d_in[6],  (const float*)d_in[7],   // Q1W2, Q1b2
        (const float*)d_in[9],  (const float*)d_in[11],  // Q2b0, Q2b1
        (const float*)d_in[12], (const float*)d_in[13],  // Q2W2, Q2b2
        (float*)d_out);
}

// round 12
// speedup vs baseline: 1.1111x; 1.1005x over previous
#include <cuda_runtime.h>
#include <cstdint>

#define BSZ   4096
#define NNODE 16
#define OBSP  10
#define HID   128
#define GPB   4          // graphs per CTA (one warp each)
#define NTH   128

typedef unsigned long long ull;
typedef unsigned int u32;

// ---- B fragments in gmem, exact mma operand order, built by prep kernel ----
// W1: [head][np(16-col tile)][ks][lane] = {b0_t0, b1_t0, b0_t1, b1_t1}
__device__ uint4 g_bfragH[2][8][8][32];
__device__ uint4 g_bfragL[2][8][8][32];
// W0 (k=10 zero-padded to 16): [head][np][lane]
__device__ uint4 g_b0H[2][8][32];
__device__ uint4 g_b0L[2][8][32];

// ---------------- mma.sync (sm_80+ portable) ----------------
#define MMA_BF16(d, a, b0, b1) \
    asm volatile("mma.sync.aligned.m16n8k16.row.col.f32.bf16.bf16.f32 " \
        "{%0,%1,%2,%3}, {%4,%5,%6,%7}, {%8,%9}, {%0,%1,%2,%3};" \
        : "+f"((d)[0]), "+f"((d)[1]), "+f"((d)[2]), "+f"((d)[3]) \
        : "r"((a)[0]), "r"((a)[1]), "r"((a)[2]), "r"((a)[3]), "r"(b0), "r"(b1))

// ---- packed f32x2 + bf16 helpers ----
__device__ __forceinline__ ull pk2(float lo, float hi) {
    ull r; asm("mov.b64 %0, {%1, %2};" : "=l"(r) : "f"(lo), "f"(hi)); return r;
}
__device__ __forceinline__ void upk2(ull v, float& lo, float& hi) {
    asm("mov.b64 {%0, %1}, %2;" : "=f"(lo), "=f"(hi) : "l"(v));
}
__device__ __forceinline__ void ffma2(ull& d, ull a, ull b) {
    asm("fma.rn.f32x2 %0, %1, %2, %0;" : "+l"(d) : "l"(a), "l"(b));
}
__device__ __forceinline__ void add2(ull& d, ull a) {
    asm("add.rn.f32x2 %0, %0, %1;" : "+l"(d) : "l"(a));
}
__device__ __forceinline__ u32 packbf(float hi_el, float lo_el) {
    u32 r; asm("cvt.rn.bf16x2.f32 %0, %1, %2;" : "=r"(r) : "f"(hi_el), "f"(lo_el));
    return r;
}
__device__ __forceinline__ float bf_lo(u32 w) { return __uint_as_float(w << 16); }
__device__ __forceinline__ float bf_hi(u32 w) { return __uint_as_float(w & 0xffff0000u); }
// split pair (f0,f1) -> hi bf16x2 + lo residual bf16x2
__device__ __forceinline__ void split2(float f0, float f1, u32& hi, u32& lo) {
    hi = packbf(f1, f0);
    lo = packbf(f1 - bf_hi(hi), f0 - bf_lo(hi));
}

// ---------------- prep kernel (merged): W1 + W0 -> bf16 hi/lo fragments --------
__global__ void __launch_bounds__(128)
prep_all(const float* __restrict__ W1a, const float* __restrict__ W1b,
         const float* __restrict__ W0a, const float* __restrict__ W0b)
{
    int id = blockIdx.x * 128 + threadIdx.x;      // 0..4607
    if (id < 4096) {
        int h  = id >> 11, np = (id >> 8) & 7, ks = (id >> 5) & 7, l = id & 31;
        const float* W1 = h ? W1b : W1a;
        int n0 = 16 * np + (l >> 2);
        int n1 = n0 + 8;
        int k0 = 16 * ks + (l & 3) * 2;
        u32 h0, h1, h2, h3, l0, l1, l2, l3;
        split2(W1[k0 * HID + n0],       W1[(k0 + 1) * HID + n0], h0, l0);
        split2(W1[(k0 + 8) * HID + n0], W1[(k0 + 9) * HID + n0], h1, l1);
        split2(W1[k0 * HID + n1],       W1[(k0 + 1) * HID + n1], h2, l2);
        split2(W1[(k0 + 8) * HID + n1], W1[(k0 + 9) * HID + n1], h3, l3);
        g_bfragH[h][np][ks][l] = make_uint4(h0, h1, h2, h3);
        g_bfragL[h][np][ks][l] = make_uint4(l0, l1, l2, l3);
    } else {
        int id2 = id - 4096;                      // 0..511
        int h  = id2 >> 8, np = (id2 >> 5) & 7, l = id2 & 31;
        const float* W0 = h ? W0b : W0a;
        int n0 = 16 * np + (l >> 2);
        int n1 = n0 + 8;
        int tig = l & 3;
        int k0 = 2 * tig;                         // 0,2,4,6 (k0+1 <= 7 < 10)
        u32 h0, h1, h2, h3, l0, l1, l2, l3;
        split2(W0[k0 * HID + n0], W0[(k0 + 1) * HID + n0], h0, l0);
        split2(W0[k0 * HID + n1], W0[(k0 + 1) * HID + n1], h2, l2);
        if (tig == 0) {                           // k0+8 = 8,9 valid only here
            split2(W0[8 * HID + n0], W0[9 * HID + n0], h1, l1);
            split2(W0[8 * HID + n1], W0[9 * HID + n1], h3, l3);
        } else { h1 = l1 = h3 = l3 = 0u; }
        g_b0H[h][np][l] = make_uint4(h0, h1, h2, h3);
        g_b0L[h][np][l] = make_uint4(l0, l1, l2, l3);
    }
}

// ---------------- main kernel ----------------
struct __align__(16) PG {
    float Ys[NNODE * 132];     // y1 fp32 [16][132]; preamble scratch aliases
    float A[NNODE][NNODE];     // normalized adjacency (symmetric)
    float Xat[OBSP][NNODE];    // (A@X) transposed
};

#define LOADROW8(dst, ptr) do { \
    const ulonglong2* _p = reinterpret_cast<const ulonglong2*>(ptr); \
    ulonglong2 _a = _p[0], _b = _p[1], _c = _p[2], _d = _p[3]; \
    dst[0]=_a.x; dst[1]=_a.y; dst[2]=_b.x; dst[3]=_b.y; \
    dst[4]=_c.x; dst[5]=_c.y; dst[6]=_d.x; dst[7]=_d.y; } while(0)

__global__ void __launch_bounds__(NTH, 4)
gcn_mma5(const float* __restrict__ obs, const float* __restrict__ act,
         const float* __restrict__ Q1b0, const float* __restrict__ Q1b1,
         const float* __restrict__ Q1W2, const float* __restrict__ Q1b2,
         const float* __restrict__ Q2b0, const float* __restrict__ Q2b1,
         const float* __restrict__ Q2W2, const float* __restrict__ Q2b2,
         float* __restrict__ out)
{
    __shared__ PG pg[GPB];
    const int tid  = threadIdx.x;
    const int warp = tid >> 5;
    const int lane = tid & 31;
    PG& P = pg[warp];
    const int g = blockIdx.x * GPB + warp;
    const int gid = lane >> 2, tig = lane & 3;
    float* Ys = P.Ys;

    // ---- per-graph preamble (warp-private; scratch aliases Ys region)
    {
        float* Xt   = P.Ys;            // [10][16]
        float* lx   = Xt + 160;
        float* ly   = Xt + 176;
        float* dinv = Xt + 192;
        const float* ob = obs + (size_t)g * (NNODE * OBSP);
        #pragma unroll
        for (int r = 0; r < 5; r++) {
            int idx = lane + 32 * r;
            float v = ob[idx];
            int n = idx / OBSP, k = idx - n * OBSP;
            if (k == 0)      lx[n] = v;
            else if (k == 1) ly[n] = v;
            else             Xt[(k - 2) * NNODE + n] = v;
        }
        float v = act[(size_t)g * (NNODE * 2) + lane];
        Xt[(8 + (lane & 1)) * NNODE + (lane >> 1)] = v;
        __syncwarp();
        #pragma unroll
        for (int r = 0; r < 8; r++) {
            int e = lane * 8 + r, i = e >> 4, j = e & 15;
            float dx = lx[i] - lx[j], dy = ly[i] - ly[j];
            P.A[i][j] = expf(-sqrtf(dx * dx + dy * dy));
        }
        __syncwarp();
        if (lane < NNODE) {
            float s = 0.f;
            #pragma unroll
            for (int j = 0; j < NNODE; j++) s += P.A[j][lane];
            dinv[lane] = rsqrtf(s);               // deg >= 1 (self loop)
        }
        __syncwarp();
        #pragma unroll
        for (int r = 0; r < 8; r++) {
            int e = lane * 8 + r, i = e >> 4, j = e & 15;
            P.A[i][j] *= dinv[i] * dinv[j];
        }
        __syncwarp();
        #pragma unroll
        for (int r = 0; r < 5; r++) {
            int idx = lane + 32 * r;              // 160 = 16 x 10
            int i = idx / OBSP, k = idx - i * OBSP;
            float s = 0.f;
            #pragma unroll
            for (int j = 0; j < NNODE; j++) s = fmaf(P.A[i][j], Xt[k * NNODE + j], s);
            P.Xat[k][i] = s;
        }
        __syncwarp();
    }

    #pragma unroll 1
    for (int q = 0; q < 2; q++) {
        const float* B0 = q ? Q2b0 : Q1b0;
        const float* B1 = q ? Q2b1 : Q1b1;
        const float* W2 = q ? Q2W2 : Q1W2;
        const float* B2 = q ? Q2b2 : Q1b2;

        // ---- Xa A-fragments (recomputed per head: keeps them short-lived)
        u32 ahX[4], alX[4];
        {
            split2(P.Xat[2 * tig][gid],     P.Xat[2 * tig + 1][gid],     ahX[0], alX[0]);
            split2(P.Xat[2 * tig][gid + 8], P.Xat[2 * tig + 1][gid + 8], ahX[1], alX[1]);
            if (tig == 0) {
                split2(P.Xat[8][gid],     P.Xat[9][gid],     ahX[2], alX[2]);
                split2(P.Xat[8][gid + 8], P.Xat[9][gid + 8], ahX[3], alX[3]);
            } else { ahX[2] = alX[2] = ahX[3] = alX[3] = 0u; }
        }

        // ==== GEMM0 (tensor): h0 = relu(Xa @ W0 + b0); D-frags become GEMM1 A-frags
        u32 ah[8][4], al[8][4];
        {
            const uint4* B0H = &g_b0H[q][0][lane];
            const uint4* B0L = &g_b0L[q][0][lane];
            #pragma unroll
            for (int np = 0; np < 8; np++) {
                float d0[4] = {0,0,0,0}, d1[4] = {0,0,0,0};
                uint4 v = __ldg(B0H + np * 32);
                uint4 w = __ldg(B0L + np * 32);
                MMA_BF16(d0, ahX, v.x, v.y);
                MMA_BF16(d0, alX, v.x, v.y);
                MMA_BF16(d0, ahX, w.x, w.y);
                MMA_BF16(d1, ahX, v.z, v.w);
                MMA_BF16(d1, alX, v.z, v.w);
                MMA_BF16(d1, ahX, w.z, w.w);
                // bias + relu; cols: d0 -> 16np+2tig,+1 ; d1 -> 16np+8+2tig,+1
                float2 b00 = __ldg(reinterpret_cast<const float2*>(B0) + 8 * np + tig);
                float2 b01 = __ldg(reinterpret_cast<const float2*>(B0) + 8 * np + 4 + tig);
                float h00 = fmaxf(d0[0] + b00.x, 0.f), h01 = fmaxf(d0[1] + b00.y, 0.f);
                float h02 = fmaxf(d0[2] + b00.x, 0.f), h03 = fmaxf(d0[3] + b00.y, 0.f);
                float h10 = fmaxf(d1[0] + b01.x, 0.f), h11 = fmaxf(d1[1] + b01.y, 0.f);
                float h12 = fmaxf(d1[2] + b01.x, 0.f), h13 = fmaxf(d1[3] + b01.y, 0.f);
                // D-frag == A-frag of GEMM1 k-tile np (rows gid/gid+8, k 2tig / +8)
                split2(h00, h01, ah[np][0], al[np][0]);
                split2(h02, h03, ah[np][1], al[np][1]);
                split2(h10, h11, ah[np][2], al[np][2]);
                split2(h12, h13, ah[np][3], al[np][3]);
            }
        }
        __syncwarp();   // prior head's Ys reads done before GEMM1 stores below

        // ==== GEMM1 (tensor): y1 = h0 @ W1, 3-term bf16 split, split accumulators
        {
            const uint4* BH = &g_bfragH[q][0][0][lane];
            const uint4* BL = &g_bfragL[q][0][0][lane];
            #pragma unroll 1
            for (int np = 0; np < 8; np++) {
                float d0[4] = {0,0,0,0}, e0[4] = {0,0,0,0};
                float d1[4] = {0,0,0,0}, e1[4] = {0,0,0,0};
                #pragma unroll
                for (int ks = 0; ks < 8; ks++) {
                    uint4 v = __ldg(BH + (np * 8 + ks) * 32);
                    uint4 w = __ldg(BL + (np * 8 + ks) * 32);
                    MMA_BF16(d0, ah[ks], v.x, v.y);
                    MMA_BF16(e0, al[ks], v.x, v.y);
                    MMA_BF16(e0, ah[ks], w.x, w.y);
                    MMA_BF16(d1, ah[ks], v.z, v.w);
                    MMA_BF16(e1, al[ks], v.z, v.w);
                    MMA_BF16(e1, ah[ks], w.z, w.w);
                }
                int col0 = 16 * np + 2 * tig;
                *reinterpret_cast<float2*>(&Ys[gid * 132 + col0])
                    = make_float2(d0[0] + e0[0], d0[1] + e0[1]);
                *reinterpret_cast<float2*>(&Ys[(gid + 8) * 132 + col0])
                    = make_float2(d0[2] + e0[2], d0[3] + e0[3]);
                *reinterpret_cast<float2*>(&Ys[gid * 132 + col0 + 8])
                    = make_float2(d1[0] + e1[0], d1[1] + e1[1]);
                *reinterpret_cast<float2*>(&Ys[(gid + 8) * 132 + col0 + 8])
                    = make_float2(d1[2] + e1[2], d1[3] + e1[3]);
            }
        }
        __syncwarp();   // cross-lane Ys visibility for agg1

        // ==== agg1 (scalar, proven): A @ y1; relu(+b1); dot W2; reduce; final agg
        {
            ull acc2[32];
            #pragma unroll
            for (int p = 0; p < 32; p++) acc2[p] = 0ull;
            #pragma unroll 4
            for (int j = 0; j < NNODE; j++) {
                float4 y4 = *reinterpret_cast<const float4*>(&Ys[j * 132 + 4 * lane]);
                ull ar[8]; LOADROW8(ar, &P.A[j][0]);
                ull yd;
                yd = pk2(y4.x, y4.x);
                #pragma unroll
                for (int m = 0; m < 8; m++) ffma2(acc2[m],      ar[m], yd);
                yd = pk2(y4.y, y4.y);
                #pragma unroll
                for (int m = 0; m < 8; m++) ffma2(acc2[8 + m],  ar[m], yd);
                yd = pk2(y4.z, y4.z);
                #pragma unroll
                for (int m = 0; m < 8; m++) ffma2(acc2[16 + m], ar[m], yd);
                yd = pk2(y4.w, y4.w);
                #pragma unroll
                for (int m = 0; m < 8; m++) ffma2(acc2[24 + m], ar[m], yd);
            }
            ull part[8];
            #pragma unroll
            for (int m = 0; m < 8; m++) part[m] = 0ull;
            {
                float4 b1v = __ldg(reinterpret_cast<const float4*>(B1) + lane);
                float4 w2v = __ldg(reinterpret_cast<const float4*>(W2) + lane);
                float bc[4] = {b1v.x, b1v.y, b1v.z, b1v.w};
                float wc[4] = {w2v.x, w2v.y, w2v.z, w2v.w};
                #pragma unroll
                for (int c = 0; c < 4; c++) {
                    ull w2d = pk2(wc[c], wc[c]);
                    #pragma unroll
                    for (int m = 0; m < 8; m++) {
                        float lo, hi; upk2(acc2[c * 8 + m], lo, hi);
                        lo = fmaxf(lo + bc[c], 0.f);
                        hi = fmaxf(hi + bc[c], 0.f);
                        ffma2(part[m], pk2(lo, hi), w2d);
                    }
                }
            }
            #pragma unroll
            for (int off = 16; off > 0; off >>= 1) {
                #pragma unroll
                for (int m = 0; m < 8; m++) {
                    ull o = __shfl_xor_sync(0xffffffffu, part[m], off);
                    add2(part[m], o);
                }
            }
            if (lane < NNODE) {
                float y2[16];
                #pragma unroll
                for (int m = 0; m < 8; m++) upk2(part[m], y2[2 * m], y2[2 * m + 1]);
                float o = __ldg(B2);
                #pragma unroll
                for (int j = 0; j < NNODE; j++)
                    o = fmaf(P.A[j][lane], y2[j], o);
                out[(size_t)q * BSZ * NNODE + (size_t)g * NNODE + lane] = o;
            }
        }
        __syncwarp();   // Ys dead before next head's GEMM1 stores
    }
}

extern "C" void kernel_launch(void* const* d_in, const int* in_sizes, int n_in,
                              void* d_out, int out_size)
{
    (void)in_sizes; (void)n_in; (void)out_size;
    prep_all<<<36, 128>>>((const float*)d_in[4], (const float*)d_in[10],
                          (const float*)d_in[2], (const float*)d_in[8]);
    gcn_mma5<<<BSZ / GPB, NTH>>>(
        (const float*)d_in[0],  (const float*)d_in[1],
        (const float*)d_in[3],  (const float*)d_in[5],   // Q1b0, Q1b1
        (const float*)d_in[6],  (const float*)d_in[7],   // Q1W2, Q1b2
        (const float*)d_in[9],  (const float*)d_in[11],  // Q2b0, Q2b1
        (const float*)d_in[12], (const float*)d_in[13],  // Q2W2, Q2b2
        (float*)d_out);
}